// round 2
// baseline (speedup 1.0000x reference)
#include <cuda_runtime.h>
#include <cstdint>

using ull = unsigned long long;

// Problem constants
constexpr int S  = 1024;   // sequence length
constexpr int HD = 256;    // hidden dim (== input dim)
constexpr int RS = 260;    // padded row stride (floats) for h/rh/x tiles (bank-conflict fix)

// SMEM layout (float offsets)
constexpr int WH_OFF = 0;              // [3][32][256] hidden weights (k-swizzled)
constexpr int WX_OFF = 24576;          // [3][32][256] input weights  (k-swizzled)
constexpr int H_OFF  = 49152;          // [8][RS] hidden state (full 256 per row)
constexpr int RH_OFF = 51232;          // [8][RS] r*h
constexpr int XB_OFF = 53312;          // [2][8][RS] x double buffer
constexpr int BI_OFF = 57472;          // [3][32] biases for own slice
constexpr int SMEM_FLOATS = 57568;
constexpr size_t SMEM_BYTES = SMEM_FLOATS * sizeof(float);   // 230272 B (< 232448 max)

__device__ __forceinline__ void ffma2(ull& d, ull a, ull b) {
    asm("fma.rn.f32x2 %0, %1, %2, %0;" : "+l"(d) : "l"(a), "l"(b));
}
__device__ __forceinline__ float2 unpk(ull a) {
    float2 r; asm("mov.b64 {%0, %1}, %2;" : "=f"(r.x), "=f"(r.y) : "l"(a)); return r;
}
__device__ __forceinline__ uint32_t smem_u32(const void* p) {
    uint32_t a;
    asm("{ .reg .u64 t; cvta.to.shared.u64 t, %1; cvt.u32.u64 %0, t; }" : "=r"(a) : "l"(p));
    return a;
}
__device__ __forceinline__ uint32_t mapa_rank(uint32_t addr, uint32_t rank) {
    uint32_t r; asm("mapa.shared::cluster.u32 %0, %1, %2;" : "=r"(r) : "r"(addr), "r"(rank));
    return r;
}
__device__ __forceinline__ void st_clu_v4(uint32_t addr, float4 v) {
    asm volatile("st.shared::cluster.v4.f32 [%0], {%1,%2,%3,%4};"
                 :: "r"(addr), "f"(v.x), "f"(v.y), "f"(v.z), "f"(v.w) : "memory");
}
__device__ __forceinline__ void clu_arrive() {
    asm volatile("barrier.cluster.arrive.aligned;" ::: "memory");
}
__device__ __forceinline__ void clu_wait() {
    asm volatile("barrier.cluster.wait.aligned;" ::: "memory");
}
__device__ __forceinline__ float sigm(float x) { return 1.0f / (1.0f + __expf(-x)); }
__device__ __forceinline__ float tanh_f(float x) {
    x = fminf(fmaxf(x, -15.0f), 15.0f);
    float e = __expf(-2.0f * x);
    return __fdividef(1.0f - e, 1.0f + e);
}

__global__ void __cluster_dims__(8, 1, 1) __launch_bounds__(256, 1)
gru_kernel(const float* __restrict__ x,   const float* __restrict__ h0,
           const float* __restrict__ Wzx, const float* __restrict__ bz, const float* __restrict__ Wzh,
           const float* __restrict__ Wrx, const float* __restrict__ b_r, const float* __restrict__ Wrh,
           const float* __restrict__ Wcx, const float* __restrict__ bc, const float* __restrict__ Wch,
           float* __restrict__ out)
{
    extern __shared__ float sm[];
    float* WH  = sm + WH_OFF;
    float* WX  = sm + WX_OFF;
    float* Hs  = sm + H_OFF;
    float* RHs = sm + RH_OFF;
    float* XBs = sm + XB_OFF;
    float* BI  = sm + BI_OFF;

    const int tid  = threadIdx.x;
    const int w    = tid >> 5;
    const int lane = tid & 31;
    const int b    = lane & 7;         // batch row within cluster
    const int ks   = lane >> 3;        // k-split chunk (0..3)
    const int jl0  = w << 2;           // warp's 4 local j columns
    const int rank = blockIdx.x & 7;   // CTA rank in cluster
    const int b0   = (blockIdx.x >> 3) << 3;  // first batch row of this cluster
    const int j0   = rank << 5;        // global j base of this CTA's slice
    const int jG   = j0 + jl0;         // global j of this warp's first column
    const int k0   = ks << 6;          // this lane's k-chunk base

    // ---------------- init: weights (k-swizzled), biases, h, x[t=0] ----------------
    {
        const float* whsrc[3] = {Wzh, Wrh, Wch};
        const float* wxsrc[3] = {Wzx, Wrx, Wcx};
        for (int g = 0; g < 3; ++g) {
            for (int i = tid; i < 32 * 64; i += 256) {
                int row = i >> 6, q = i & 63;
                int c = q >> 4, qi = q & 15;
                int pq = (qi + c) & 15;              // per-chunk quad rotation
                int dst = (g * 32 + row) * 256 + c * 64 + pq * 4;
                *(float4*)(WH + dst) = *(const float4*)(whsrc[g] + (j0 + row) * 256 + q * 4);
                *(float4*)(WX + dst) = *(const float4*)(wxsrc[g] + (j0 + row) * 256 + q * 4);
            }
        }
        if (tid < 32) {
            BI[tid]      = bz[j0 + tid];
            BI[32 + tid] = b_r[j0 + tid];
            BI[64 + tid] = bc[j0 + tid];
        }
        for (int i = tid; i < 8 * 64; i += 256) {
            int bb = i >> 6, q = i & 63;
            *(float4*)(Hs  + bb * RS + q * 4) = *(const float4*)(h0 + (b0 + bb) * HD + q * 4);
            *(float4*)(XBs + bb * RS + q * 4) =
                *(const float4*)(x + (size_t)(b0 + bb) * S * HD + q * 4);
        }
    }
    __syncthreads();
    clu_arrive(); clu_wait();

    // Precomputed DSMEM addresses for the 8 cluster ranks (fixed per (b, jG))
    const uint32_t base = smem_u32(sm);
    uint32_t rh_addr[8], h_addr[8];
#pragma unroll
    for (int p = 0; p < 8; ++p) {
        rh_addr[p] = mapa_rank(base + (uint32_t)(RH_OFF + b * RS + jG) * 4u, p);
        h_addr[p]  = mapa_rank(base + (uint32_t)(H_OFF  + b * RS + jG) * 4u, p);
    }
    float* outp = out + (size_t)(b0 + b) * S * HD + jG;
    const float* xsrc = x + (size_t)(b0 + (tid >> 5)) * S * HD + (tid & 31) * 8;

    const float* Hrow = Hs + b * RS;

    for (int t = 0; t < S; ++t) {
        // prefetch x_{t+1} (global -> regs; STS later this step)
        float4 px0, px1;
        if (t + 1 < S) {
            const float* p = xsrc + (size_t)(t + 1) * HD;
            px0 = *(const float4*)p;
            px1 = *(const float4*)(p + 4);
        }
        const float* Xrow = XBs + (t & 1) * (8 * RS) + b * RS;

        // ---------- sub-phase 1: z and r gates (h-part + x-part) ----------
        ull acc[8];
#pragma unroll
        for (int i = 0; i < 8; ++i) acc[i] = 0ull;
#pragma unroll
        for (int kq = 0; kq < 16; ++kq) {
            const int kk = k0 + kq * 4;
            const int kw = k0 + (((kq + ks) & 15) << 2);   // swizzled W position
            ulonglong2 hv = *(const ulonglong2*)(Hrow + kk);
            ulonglong2 xv = *(const ulonglong2*)(Xrow + kk);
#pragma unroll
            for (int g = 0; g < 2; ++g) {
#pragma unroll
                for (int jj = 0; jj < 4; ++jj) {
                    const int ro = (g * 32 + jl0 + jj) * 256 + kw;
                    ulonglong2 wh = *(const ulonglong2*)(WH + ro);
                    ffma2(acc[g * 4 + jj], hv.x, wh.x);
                    ffma2(acc[g * 4 + jj], hv.y, wh.y);
                    ulonglong2 wx2 = *(const ulonglong2*)(WX + ro);
                    ffma2(acc[g * 4 + jj], xv.x, wx2.x);
                    ffma2(acc[g * 4 + jj], xv.y, wx2.y);
                }
            }
        }
        float sv[8];
#pragma unroll
        for (int o = 0; o < 8; ++o) {
            float2 f = unpk(acc[o]);
            float s = f.x + f.y;
            s += __shfl_xor_sync(0xffffffffu, s, 8);
            s += __shfl_xor_sync(0xffffffffu, s, 16);
            sv[o] = s;
        }
        float hprev[4], zg[4], r4[4];
#pragma unroll
        for (int jj = 0; jj < 4; ++jj) hprev[jj] = Hrow[jG + jj];
#pragma unroll
        for (int jj = 0; jj < 4; ++jj) zg[jj] = sigm(sv[jj] + BI[jl0 + jj]);
#pragma unroll
        for (int jj = 0; jj < 4; ++jj) {
            float r = sigm(sv[4 + jj] + BI[32 + jl0 + jj]);
            r4[jj] = r * hprev[jj];
        }
        if (ks == 0) {
            float4 rhv = make_float4(r4[0], r4[1], r4[2], r4[3]);
#pragma unroll
            for (int p = 0; p < 8; ++p) st_clu_v4(rh_addr[p], rhv);
        }
        clu_arrive();
        // overlap: commit x_{t+1} to the other buffer while the cluster drains
        if (t + 1 < S) {
            float* xd = XBs + ((t + 1) & 1) * (8 * RS) + (tid >> 5) * RS + (tid & 31) * 8;
            *(float4*)xd       = px0;
            *(float4*)(xd + 4) = px1;
        }
        clu_wait();

        // ---------- sub-phase 2: candidate gate c ----------
        const float* Rrow = RHs + b * RS;
        ull cacc[4] = {0ull, 0ull, 0ull, 0ull};
#pragma unroll
        for (int kq = 0; kq < 16; ++kq) {
            const int kk = k0 + kq * 4;
            const int kw = k0 + (((kq + ks) & 15) << 2);
            ulonglong2 rv = *(const ulonglong2*)(Rrow + kk);
            ulonglong2 xv = *(const ulonglong2*)(Xrow + kk);
#pragma unroll
            for (int jj = 0; jj < 4; ++jj) {
                const int ro = (64 + jl0 + jj) * 256 + kw;
                ulonglong2 wh = *(const ulonglong2*)(WH + ro);
                ffma2(cacc[jj], rv.x, wh.x);
                ffma2(cacc[jj], rv.y, wh.y);
                ulonglong2 wx2 = *(const ulonglong2*)(WX + ro);
                ffma2(cacc[jj], xv.x, wx2.x);
                ffma2(cacc[jj], xv.y, wx2.y);
            }
        }
        float hn[4];
#pragma unroll
        for (int jj = 0; jj < 4; ++jj) {
            float2 f = unpk(cacc[jj]);
            float s = f.x + f.y;
            s += __shfl_xor_sync(0xffffffffu, s, 8);
            s += __shfl_xor_sync(0xffffffffu, s, 16);
            float ct = tanh_f(s + BI[64 + jl0 + jj]);
            hn[jj] = fmaf(zg[jj], ct - hprev[jj], hprev[jj]);   // (1-z)h + z*ct
        }
        if (ks == 0) {
            float4 hv4 = make_float4(hn[0], hn[1], hn[2], hn[3]);
#pragma unroll
            for (int p = 0; p < 8; ++p) st_clu_v4(h_addr[p], hv4);
            *(float4*)(outp + (size_t)t * HD) = hv4;
        }
        clu_arrive();
        clu_wait();
    }
}

extern "C" void kernel_launch(void* const* d_in, const int* in_sizes, int n_in,
                              void* d_out, int out_size) {
    const float* x   = (const float*)d_in[0];
    const float* h0  = (const float*)d_in[1];
    const float* Wzx = (const float*)d_in[2];
    const float* bz  = (const float*)d_in[3];
    const float* Wzh = (const float*)d_in[4];
    const float* Wrx = (const float*)d_in[5];
    const float* br  = (const float*)d_in[6];
    const float* Wrh = (const float*)d_in[7];
    const float* Wcx = (const float*)d_in[8];
    const float* bc  = (const float*)d_in[9];
    const float* Wch = (const float*)d_in[10];
    float* out = (float*)d_out;

    cudaFuncSetAttribute(gru_kernel, cudaFuncAttributeMaxDynamicSharedMemorySize,
                         (int)SMEM_BYTES);
    // 16 clusters of 8 CTAs (static __cluster_dims__), 8 batch rows per cluster
    gru_kernel<<<128, 256, SMEM_BYTES>>>(x, h0, Wzx, bz, Wzh, Wrx, br, Wrh,
                                         Wcx, bc, Wch, out);
}

// round 3
// speedup vs baseline: 2.0297x; 2.0297x over previous
#include <cuda_runtime.h>
#include <cstdint>

using ull = unsigned long long;

constexpr int S  = 1024;
constexpr int HD = 256;
constexpr int NB = 128;

// Precomputed input projections: XG[b][s][gate*256 + j], gate order z,r,c
__device__ float XG_buf[(size_t)NB * S * 768];

__device__ __forceinline__ void ffma2(ull& d, ull a, ull b) {
    asm("fma.rn.f32x2 %0, %1, %2, %0;" : "+l"(d) : "l"(a), "l"(b));
}
__device__ __forceinline__ float2 unpk(ull a) {
    float2 r; asm("mov.b64 {%0, %1}, %2;" : "=f"(r.x), "=f"(r.y) : "l"(a)); return r;
}
__device__ __forceinline__ uint32_t smem_u32(const void* p) {
    uint32_t a;
    asm("{ .reg .u64 t; cvta.to.shared.u64 t, %1; cvt.u32.u64 %0, t; }" : "=r"(a) : "l"(p));
    return a;
}
__device__ __forceinline__ uint32_t mapa_rank(uint32_t addr, uint32_t rank) {
    uint32_t r; asm("mapa.shared::cluster.u32 %0, %1, %2;" : "=r"(r) : "r"(addr), "r"(rank));
    return r;
}
__device__ __forceinline__ void st_clu_v4(uint32_t addr, float4 v) {
    asm volatile("st.shared::cluster.v4.f32 [%0], {%1,%2,%3,%4};"
                 :: "r"(addr), "f"(v.x), "f"(v.y), "f"(v.z), "f"(v.w) : "memory");
}
__device__ __forceinline__ void clu_arrive() {
    asm volatile("barrier.cluster.arrive.aligned;" ::: "memory");
}
__device__ __forceinline__ void clu_wait() {
    asm volatile("barrier.cluster.wait.aligned;" ::: "memory");
}
__device__ __forceinline__ float sigm(float x) { return 1.0f / (1.0f + __expf(-x)); }
__device__ __forceinline__ float tanh_f(float x) {
    x = fminf(fmaxf(x, -15.0f), 15.0f);
    float e = __expf(-2.0f * x);
    return __fdividef(1.0f - e, 1.0f + e);
}
// quad rotation swizzle: logical quad q (0..63) -> phys quad within a 256-float row
__device__ __forceinline__ int swq(int q) { return (q & ~7) | ((q + (q >> 3)) & 7); }

// ============================================================================
// Phase 1: XG = x @ Wg^T + bias for all 3 gates, full chip, FFMA2 GEMM.
// grid = 12 n-tiles * 128 m-groups; each CTA: W tile resident, loops 8 m-tiles.
// ============================================================================
constexpr int PRE_SMEM_FLOATS = 32768 + 64 * 260;   // x tile [128][256] + W [64][260]
constexpr size_t PRE_SMEM_BYTES = PRE_SMEM_FLOATS * sizeof(float);

__global__ void __launch_bounds__(256, 1)
xproj_kernel(const float* __restrict__ x,
             const float* __restrict__ Wzx, const float* __restrict__ bz,
             const float* __restrict__ Wrx, const float* __restrict__ br,
             const float* __restrict__ Wcx, const float* __restrict__ bc)
{
    extern __shared__ float smp[];
    float* XS = smp;            // [128][256]
    float* WS = smp + 32768;    // [64][260]

    const int tid = threadIdx.x, w = tid >> 5, lane = tid & 31;
    const int nt = blockIdx.x % 12, mg = blockIdx.x / 12;
    const int gate = nt >> 2, j0 = (nt & 3) * 64;

    const float* Wsrc = (gate == 0 ? Wzx : (gate == 1 ? Wrx : Wcx)) + (size_t)j0 * HD;
    const float* bsrc = (gate == 0 ? bz : (gate == 1 ? br : bc)) + j0;
    const float b0v = bsrc[lane];
    const float b1v = bsrc[lane + 32];

    // load W tile once (64 rows, padded stride 260)
    for (int i = tid; i < 64 * 64; i += 256) {
        int row = i >> 6, q = i & 63;
        *(float4*)(WS + row * 260 + q * 4) = *(const float4*)(Wsrc + row * 256 + q * 4);
    }

    const int r0 = w * 16;
    for (int it = 0; it < 8; ++it) {
        const int m = mg * 8 + it;
        __syncthreads();   // XS safe to overwrite
        const float* xs = x + (size_t)m * 128 * HD;
#pragma unroll 8
        for (int i = tid; i < 8192; i += 256)
            *(float4*)(XS + i * 4) = *(const float4*)(xs + (size_t)i * 4);
        __syncthreads();

        ull acc[32];
#pragma unroll
        for (int i = 0; i < 32; ++i) acc[i] = 0ull;

#pragma unroll 4
        for (int kq = 0; kq < 64; ++kq) {
            ulonglong2 wv0 = *(const ulonglong2*)(WS + lane * 260 + kq * 4);
            ulonglong2 wv1 = *(const ulonglong2*)(WS + (lane + 32) * 260 + kq * 4);
#pragma unroll
            for (int r = 0; r < 16; ++r) {
                ulonglong2 xv = *(const ulonglong2*)(XS + (r0 + r) * 256 + kq * 4);
                ffma2(acc[r * 2 + 0], xv.x, wv0.x);
                ffma2(acc[r * 2 + 0], xv.y, wv0.y);
                ffma2(acc[r * 2 + 1], xv.x, wv1.x);
                ffma2(acc[r * 2 + 1], xv.y, wv1.y);
            }
        }

        float* op = XG_buf + ((size_t)m * 128 + r0) * 768 + gate * 256 + j0;
#pragma unroll
        for (int r = 0; r < 16; ++r) {
            float2 f0 = unpk(acc[r * 2 + 0]);
            float2 f1 = unpk(acc[r * 2 + 1]);
            op[(size_t)r * 768 + lane]      = f0.x + f0.y + b0v;
            op[(size_t)r * 768 + lane + 32] = f1.x + f1.y + b1v;
        }
    }
}

// ============================================================================
// Phase 2: recurrence. 32 clusters x 4 CTAs; cluster owns 4 batch rows,
// CTA owns a 64-wide j slice of all 3 gates. Wh resident in SMEM (192KB).
// ============================================================================
constexpr int WH_OFF = 0;          // [192][256] hidden weights, quad-swizzled rows
constexpr int H_OFF  = 49152;      // [4][260]
constexpr int RH_OFF = 50192;      // [4][260]
constexpr int REC_SMEM_FLOATS = 51232;
constexpr size_t REC_SMEM_BYTES = REC_SMEM_FLOATS * sizeof(float);  // 204928

__global__ void __cluster_dims__(4, 1, 1) __launch_bounds__(256, 1)
gru_rec(const float* __restrict__ h0,
        const float* __restrict__ Wzh, const float* __restrict__ Wrh,
        const float* __restrict__ Wch, float* __restrict__ out)
{
    extern __shared__ float sm[];
    float* WH  = sm + WH_OFF;
    float* Hs  = sm + H_OFF;
    float* RHs = sm + RH_OFF;

    const int tid  = threadIdx.x;
    const int w    = tid >> 5;
    const int lane = tid & 31;
    const int b    = lane & 3;       // batch row within cluster
    const int ks   = lane >> 2;      // k-split (0..7), 32 floats each
    const int rank = blockIdx.x & 3;
    const int b0   = (blockIdx.x >> 2) << 2;
    const int j0   = rank << 6;
    const int jG   = j0 + w * 8;     // this warp's first global j column

    // ---- init: Wh slices (quad-swizzled) and h0 ----
    {
        const float* whs[3] = {Wzh, Wrh, Wch};
        for (int i = tid; i < 12288; i += 256) {
            int g = i >> 12, rem = i & 4095, row = rem >> 6, q = rem & 63;
            *(float4*)(WH + (g * 64 + row) * 256 + swq(q) * 4) =
                *(const float4*)(whs[g] + (size_t)(j0 + row) * 256 + q * 4);
        }
        int bb = tid >> 6, q = tid & 63;
        *(float4*)(Hs + bb * 260 + swq(q) * 4) =
            *(const float4*)(h0 + (size_t)(b0 + bb) * 256 + q * 4);
    }
    __syncthreads();
    clu_arrive(); clu_wait();

    // DSMEM push addresses (meaningful for lanes 0..3 only): 2 quads x 4 ranks
    const uint32_t base = smem_u32(sm);
    const int jq0 = jG >> 2;
    uint32_t rh_a[8], h_a[8];
#pragma unroll
    for (int qq = 0; qq < 2; ++qq) {
        uint32_t offR = (uint32_t)(RH_OFF + b * 260 + swq(jq0 + qq) * 4) * 4u;
        uint32_t offH = (uint32_t)(H_OFF  + b * 260 + swq(jq0 + qq) * 4) * 4u;
#pragma unroll
        for (int p = 0; p < 4; ++p) {
            rh_a[qq * 4 + p] = mapa_rank(base + offR, p);
            h_a [qq * 4 + p] = mapa_rank(base + offH, p);
        }
    }

    // hprev held in registers by the output lanes (lane<4)
    float hprev[8];
    if (lane < 4) {
#pragma unroll
        for (int jj = 0; jj < 8; ++jj) {
            int q = jq0 + (jj >> 2);
            hprev[jj] = Hs[b * 260 + swq(q) * 4 + (jj & 3)];
        }
    }

    const float* Hb = Hs + b * 260;
    const float* Rb = RHs + b * 260;
    const float* XGp = XG_buf + (size_t)(b0 + b) * S * 768 + jG;
    float* outb = out + (size_t)(b0 + b) * S * 256 + jG;

    float zg[8];

    for (int t = 0; t < S; ++t) {
        // prefetch this step's input-side gate values (L2) — output lanes only
        float xzf[8], xrf[8], xcf[8];
        if (lane < 4) {
            const float* p = XGp + (size_t)t * 768;
            float4 a0 = *(const float4*)(p);       float4 a1 = *(const float4*)(p + 4);
            float4 r0 = *(const float4*)(p + 256); float4 r1 = *(const float4*)(p + 260);
            float4 c0 = *(const float4*)(p + 512); float4 c1 = *(const float4*)(p + 516);
            xzf[0]=a0.x; xzf[1]=a0.y; xzf[2]=a0.z; xzf[3]=a0.w;
            xzf[4]=a1.x; xzf[5]=a1.y; xzf[6]=a1.z; xzf[7]=a1.w;
            xrf[0]=r0.x; xrf[1]=r0.y; xrf[2]=r0.z; xrf[3]=r0.w;
            xrf[4]=r1.x; xrf[5]=r1.y; xrf[6]=r1.z; xrf[7]=r1.w;
            xcf[0]=c0.x; xcf[1]=c0.y; xcf[2]=c0.z; xcf[3]=c0.w;
            xcf[4]=c1.x; xcf[5]=c1.y; xcf[6]=c1.z; xcf[7]=c1.w;
        }

        // ---------- phase 1: z and r gates (h-part) ----------
        ull acc[16];
#pragma unroll
        for (int i = 0; i < 16; ++i) acc[i] = 0ull;
#pragma unroll
        for (int kq = 0; kq < 8; ++kq) {
            const int pq = ks * 8 + ((kq + ks) & 7);
            ulonglong2 hv = *(const ulonglong2*)(Hb + pq * 4);
            const float* wp = WH + (w * 8) * 256 + pq * 4;
#pragma unroll
            for (int g = 0; g < 2; ++g)
#pragma unroll
                for (int jj = 0; jj < 8; ++jj) {
                    ulonglong2 wv = *(const ulonglong2*)(wp + (g * 64 + jj) * 256);
                    ffma2(acc[g * 8 + jj], hv.x, wv.x);
                    ffma2(acc[g * 8 + jj], hv.y, wv.y);
                }
        }
        float sv[16];
#pragma unroll
        for (int o = 0; o < 16; ++o) {
            float2 f = unpk(acc[o]);
            float s = f.x + f.y;
            s += __shfl_xor_sync(0xffffffffu, s, 4);
            s += __shfl_xor_sync(0xffffffffu, s, 8);
            s += __shfl_xor_sync(0xffffffffu, s, 16);
            sv[o] = s;
        }
        if (lane < 4) {
            float rr[8];
#pragma unroll
            for (int jj = 0; jj < 8; ++jj) zg[jj] = sigm(sv[jj] + xzf[jj]);
#pragma unroll
            for (int jj = 0; jj < 8; ++jj)
                rr[jj] = sigm(sv[8 + jj] + xrf[jj]) * hprev[jj];
            float4 q0 = make_float4(rr[0], rr[1], rr[2], rr[3]);
            float4 q1 = make_float4(rr[4], rr[5], rr[6], rr[7]);
#pragma unroll
            for (int p = 0; p < 4; ++p) { st_clu_v4(rh_a[p], q0); st_clu_v4(rh_a[4 + p], q1); }
        }
        clu_arrive(); clu_wait();

        // ---------- phase 2: candidate gate ----------
        ull cacc[8];
#pragma unroll
        for (int i = 0; i < 8; ++i) cacc[i] = 0ull;
#pragma unroll
        for (int kq = 0; kq < 8; ++kq) {
            const int pq = ks * 8 + ((kq + ks) & 7);
            ulonglong2 rv = *(const ulonglong2*)(Rb + pq * 4);
            const float* wp = WH + (128 + w * 8) * 256 + pq * 4;
#pragma unroll
            for (int jj = 0; jj < 8; ++jj) {
                ulonglong2 wv = *(const ulonglong2*)(wp + jj * 256);
                ffma2(cacc[jj], rv.x, wv.x);
                ffma2(cacc[jj], rv.y, wv.y);
            }
        }
        float cv[8];
#pragma unroll
        for (int o = 0; o < 8; ++o) {
            float2 f = unpk(cacc[o]);
            float s = f.x + f.y;
            s += __shfl_xor_sync(0xffffffffu, s, 4);
            s += __shfl_xor_sync(0xffffffffu, s, 8);
            s += __shfl_xor_sync(0xffffffffu, s, 16);
            cv[o] = s;
        }
        if (lane < 4) {
            float hn[8];
#pragma unroll
            for (int jj = 0; jj < 8; ++jj) {
                float ct = tanh_f(cv[jj] + xcf[jj]);
                hn[jj] = fmaf(zg[jj], ct - hprev[jj], hprev[jj]);
                hprev[jj] = hn[jj];
            }
            float4 q0 = make_float4(hn[0], hn[1], hn[2], hn[3]);
            float4 q1 = make_float4(hn[4], hn[5], hn[6], hn[7]);
#pragma unroll
            for (int p = 0; p < 4; ++p) { st_clu_v4(h_a[p], q0); st_clu_v4(h_a[4 + p], q1); }
            float* op = outb + (size_t)t * 256;
            *(float4*)op       = q0;
            *(float4*)(op + 4) = q1;
        }
        clu_arrive(); clu_wait();
    }
}

extern "C" void kernel_launch(void* const* d_in, const int* in_sizes, int n_in,
                              void* d_out, int out_size) {
    const float* x   = (const float*)d_in[0];
    const float* h0  = (const float*)d_in[1];
    const float* Wzx = (const float*)d_in[2];
    const float* bz  = (const float*)d_in[3];
    const float* Wzh = (const float*)d_in[4];
    const float* Wrx = (const float*)d_in[5];
    const float* br  = (const float*)d_in[6];
    const float* Wrh = (const float*)d_in[7];
    const float* Wcx = (const float*)d_in[8];
    const float* bc  = (const float*)d_in[9];
    const float* Wch = (const float*)d_in[10];
    float* out = (float*)d_out;

    cudaFuncSetAttribute(xproj_kernel, cudaFuncAttributeMaxDynamicSharedMemorySize,
                         (int)PRE_SMEM_BYTES);
    cudaFuncSetAttribute(gru_rec, cudaFuncAttributeMaxDynamicSharedMemorySize,
                         (int)REC_SMEM_BYTES);

    // Phase 1: input projections for all timesteps (full chip, parallel)
    xproj_kernel<<<12 * 128, 256, PRE_SMEM_BYTES>>>(x, Wzx, bz, Wrx, br, Wcx, bc);
    // Phase 2: sequential recurrence (32 clusters of 4 CTAs)
    gru_rec<<<128, 256, REC_SMEM_BYTES>>>(h0, Wzh, Wrh, Wch, out);
}